// round 1
// baseline (speedup 1.0000x reference)
#include <cuda_runtime.h>

#define N_NODES 50000
#define N_EDGES 800000
#define D 64

// Scratch (allocation-free rule: static __device__ globals, zero-initialized at load)
__device__ float g_agg[(size_t)N_NODES * D];
__device__ float g_h1[(size_t)N_NODES * D];
__device__ float g_h2[(size_t)N_NODES * D];
__device__ float g_deg[N_NODES];
__device__ float g_inv[N_NODES];

// ---------------------------------------------------------------------------
// In-degree count. g_deg must be zero on entry; inv_kernel re-zeros it so the
// captured graph is replayable (deterministic same-work-every-call).
__global__ void deg_kernel(const int* __restrict__ dst) {
    int e = blockIdx.x * blockDim.x + threadIdx.x;
    if (e < N_EDGES) atomicAdd(&g_deg[dst[e]], 1.0f);
}

__global__ void inv_kernel() {
    int n = blockIdx.x * blockDim.x + threadIdx.x;
    if (n < N_NODES) {
        g_inv[n] = 1.0f / (g_deg[n] + 1.0f);
        g_deg[n] = 0.0f;  // ready for next replay
    }
}

// ---------------------------------------------------------------------------
// Edge scatter: agg[dst] += h[src]. 16 threads per edge, one float4 each.
// Gather is an L2-hit LDG.128 (12.8MB feature table resides in L2); scatter is
// a no-return vector reduction (REDG path).
__global__ void __launch_bounds__(256) scatter_kernel(
        const float* __restrict__ h,
        const int* __restrict__ src,
        const int* __restrict__ dst) {
    int idx = blockIdx.x * blockDim.x + threadIdx.x;
    int e = idx >> 4;
    if (e >= N_EDGES) return;
    int q = idx & 15;
    int s = __ldg(src + e);
    int d = __ldg(dst + e);
    float4 v = __ldg(reinterpret_cast<const float4*>(h + (size_t)s * D) + q);
    float* p = g_agg + (size_t)d * D + (size_t)q * 4;
    asm volatile("red.global.add.v4.f32 [%0], {%1, %2, %3, %4};"
                 :: "l"(p), "f"(v.x), "f"(v.y), "f"(v.z), "f"(v.w)
                 : "memory");
}

// ---------------------------------------------------------------------------
// Fused: v = (agg + h) * inv ; out = relu?(v @ W + b). Warp-per-row.
// Also zeroes g_agg behind itself (each agg element is read exactly once here)
// so the next layer's scatter starts from a clean accumulator.
template <bool RELU>
__global__ void __launch_bounds__(256) mlp_kernel(
        const float* __restrict__ h,
        const float* __restrict__ W,
        const float* __restrict__ b,
        float* __restrict__ out) {
    __shared__ float Ws[D * D];
    __shared__ float bs[D];
    int tid = threadIdx.x;
    for (int i = tid; i < D * D; i += 256) Ws[i] = W[i];
    if (tid < D) bs[tid] = b[tid];
    __syncthreads();

    int warp = tid >> 5;
    int lane = tid & 31;
    int row = blockIdx.x * 8 + warp;
    if (row >= N_NODES) return;

    float invr = g_inv[row];
    size_t base = (size_t)row * D;

    float va = (g_agg[base + lane]      + h[base + lane])      * invr;
    float vb = (g_agg[base + lane + 32] + h[base + lane + 32]) * invr;
    g_agg[base + lane]      = 0.0f;
    g_agg[base + lane + 32] = 0.0f;

    float acc0 = bs[lane];
    float acc1 = bs[lane + 32];
#pragma unroll
    for (int k = 0; k < 32; k++) {
        float vk = __shfl_sync(0xffffffffu, va, k);
        acc0 += vk * Ws[k * D + lane];
        acc1 += vk * Ws[k * D + lane + 32];
    }
#pragma unroll
    for (int k = 0; k < 32; k++) {
        float vk = __shfl_sync(0xffffffffu, vb, k);
        acc0 += vk * Ws[(k + 32) * D + lane];
        acc1 += vk * Ws[(k + 32) * D + lane + 32];
    }
    if (RELU) {
        acc0 = fmaxf(acc0, 0.0f);
        acc1 = fmaxf(acc1, 0.0f);
    }
    out[base + lane]      = acc0;
    out[base + lane + 32] = acc1;
}

// ---------------------------------------------------------------------------
extern "C" void kernel_launch(void* const* d_in, const int* in_sizes, int n_in,
                              void* d_out, int out_size) {
    const float* x   = (const float*)d_in[0];
    const int*   src = (const int*)  d_in[1];
    const int*   dst = (const int*)  d_in[2];
    const float* W0  = (const float*)d_in[3];
    const float* b0  = (const float*)d_in[4];
    const float* W1  = (const float*)d_in[5];
    const float* b1  = (const float*)d_in[6];
    const float* W2  = (const float*)d_in[7];
    const float* b2  = (const float*)d_in[8];
    float* out = (float*)d_out;

    float* h1;  cudaGetSymbolAddress((void**)&h1, g_h1);
    float* h2;  cudaGetSymbolAddress((void**)&h2, g_h2);

    const int scatter_grid = (N_EDGES * 16 + 255) / 256;  // 50000
    const int mlp_grid     = (N_NODES + 7) / 8;           // 6250

    // degree + normalizer (g_deg zeroed by inv_kernel for graph replay)
    deg_kernel<<<(N_EDGES + 255) / 256, 256>>>(dst);
    inv_kernel<<<(N_NODES + 255) / 256, 256>>>();

    // layer 0
    scatter_kernel<<<scatter_grid, 256>>>(x, src, dst);
    mlp_kernel<true><<<mlp_grid, 256>>>(x, W0, b0, h1);

    // layer 1
    scatter_kernel<<<scatter_grid, 256>>>(h1, src, dst);
    mlp_kernel<true><<<mlp_grid, 256>>>(h1, W1, b1, h2);

    // layer 2
    scatter_kernel<<<scatter_grid, 256>>>(h2, src, dst);
    mlp_kernel<false><<<mlp_grid, 256>>>(h2, W2, b2, out);
}

// round 2
// speedup vs baseline: 1.0784x; 1.0784x over previous
#include <cuda_runtime.h>

#define N_NODES 50000
#define N_EDGES 800000
#define D 64
#define TR 64            // rows per MLP block
#define WSTRIDE 68       // padded W row stride (272B = 17*16B: float4-aligned, conflict-free)

// Scratch (allocation-free rule: __device__ globals, zero-initialized at load)
__device__ float g_agg[(size_t)N_NODES * D];
__device__ float g_h1[(size_t)N_NODES * D];
__device__ float g_h2[(size_t)N_NODES * D];
__device__ float g_deg[N_NODES];
__device__ float g_inv[N_NODES];

// ---------------------------------------------------------------------------
// In-degree count. g_deg zero on entry; inv_kernel re-zeros it for graph replay.
__global__ void deg_kernel(const int* __restrict__ dst) {
    int e = blockIdx.x * blockDim.x + threadIdx.x;
    if (e < N_EDGES) atomicAdd(&g_deg[dst[e]], 1.0f);
}

__global__ void inv_kernel() {
    int n = blockIdx.x * blockDim.x + threadIdx.x;
    if (n < N_NODES) {
        g_inv[n] = 1.0f / (g_deg[n] + 1.0f);
        g_deg[n] = 0.0f;  // ready for next replay
    }
}

// ---------------------------------------------------------------------------
// Edge scatter: agg[dst] += h[src]. 16 threads/edge, one float4 each.
// Gather = L2-hit LDG.128 (12.8MB table L2-resident); scatter = REDG.v4.
__global__ void __launch_bounds__(256) scatter_kernel(
        const float* __restrict__ h,
        const int* __restrict__ src,
        const int* __restrict__ dst) {
    int idx = blockIdx.x * blockDim.x + threadIdx.x;
    int e = idx >> 4;
    if (e >= N_EDGES) return;
    int q = idx & 15;
    int s = __ldg(src + e);
    int d = __ldg(dst + e);
    float4 v = __ldg(reinterpret_cast<const float4*>(h + (size_t)s * D) + q);
    float* p = g_agg + (size_t)d * D + (size_t)q * 4;
    asm volatile("red.global.add.v4.f32 [%0], {%1, %2, %3, %4};"
                 :: "l"(p), "f"(v.x), "f"(v.y), "f"(v.z), "f"(v.w)
                 : "memory");
}

// ---------------------------------------------------------------------------
// Fused: v = (agg + h) * inv ; out = relu?(v @ W + b).
// Register-blocked GEMM: block stages 64-row v tile + transposed padded W in
// smem; each warp computes 8 rows x 64 cols with 10 LDS.128 per 64 FMAs.
// Zeroes g_agg behind itself (each element read exactly once).
template <bool RELU>
__global__ void __launch_bounds__(256) mlp_kernel(
        const float* __restrict__ h,
        const float* __restrict__ W,
        const float* __restrict__ b,
        float* __restrict__ out) {
    __shared__ float Wsm[D * WSTRIDE];   // Wsm[c*WSTRIDE + k] = W[k][c]
    __shared__ float vsm[TR * D];        // vsm[r*D + k]
    __shared__ float bs[D];

    int tid = threadIdx.x;
    int rowBase = blockIdx.x * TR;

    // Load W transposed (one-time, minor bank conflicts OK)
    for (int i = tid; i < D * D; i += 256) {
        int k = i >> 6, c = i & 63;
        Wsm[c * WSTRIDE + k] = W[i];
    }
    if (tid < D) bs[tid] = b[tid];

    // Stage v tile: (agg + h) * inv, float4-granular, coalesced; zero agg behind.
    for (int i = tid; i < TR * (D / 4); i += 256) {     // 1024 float4s
        int r = i >> 4;
        int row = rowBase + r;
        if (row < N_NODES) {
            size_t off = (size_t)row * D + (size_t)(i & 15) * 4;
            float4 a  = *reinterpret_cast<float4*>(g_agg + off);
            float4 hh = __ldg(reinterpret_cast<const float4*>(h + off));
            float iv = g_inv[row];
            float4 v;
            v.x = (a.x + hh.x) * iv;
            v.y = (a.y + hh.y) * iv;
            v.z = (a.z + hh.z) * iv;
            v.w = (a.w + hh.w) * iv;
            *reinterpret_cast<float4*>(vsm + (size_t)i * 4) = v;
            *reinterpret_cast<float4*>(g_agg + off) = make_float4(0.f, 0.f, 0.f, 0.f);
        }
    }
    __syncthreads();

    int warp = tid >> 5;
    int lane = tid & 31;
    int r0 = warp * 8;

    float acc0[8], acc1[8];
#pragma unroll
    for (int r = 0; r < 8; r++) { acc0[r] = bs[lane]; acc1[r] = bs[lane + 32]; }

    const float4* wrow_a = reinterpret_cast<const float4*>(Wsm + lane * WSTRIDE);
    const float4* wrow_b = reinterpret_cast<const float4*>(Wsm + (lane + 32) * WSTRIDE);

#pragma unroll
    for (int ch = 0; ch < 16; ch++) {
        float4 wa = wrow_a[ch];   // W[4ch..4ch+3][lane]      (conflict-free)
        float4 wb = wrow_b[ch];   // W[4ch..4ch+3][lane+32]
#pragma unroll
        for (int r = 0; r < 8; r++) {
            float4 v = *reinterpret_cast<const float4*>(vsm + (r0 + r) * D + ch * 4); // broadcast
            acc0[r] = fmaf(v.x, wa.x, acc0[r]);
            acc0[r] = fmaf(v.y, wa.y, acc0[r]);
            acc0[r] = fmaf(v.z, wa.z, acc0[r]);
            acc0[r] = fmaf(v.w, wa.w, acc0[r]);
            acc1[r] = fmaf(v.x, wb.x, acc1[r]);
            acc1[r] = fmaf(v.y, wb.y, acc1[r]);
            acc1[r] = fmaf(v.z, wb.z, acc1[r]);
            acc1[r] = fmaf(v.w, wb.w, acc1[r]);
        }
    }

#pragma unroll
    for (int r = 0; r < 8; r++) {
        int row = rowBase + r0 + r;
        if (row < N_NODES) {
            float o0 = acc0[r], o1 = acc1[r];
            if (RELU) { o0 = fmaxf(o0, 0.f); o1 = fmaxf(o1, 0.f); }
            out[(size_t)row * D + lane]      = o0;
            out[(size_t)row * D + lane + 32] = o1;
        }
    }
}

// ---------------------------------------------------------------------------
extern "C" void kernel_launch(void* const* d_in, const int* in_sizes, int n_in,
                              void* d_out, int out_size) {
    const float* x   = (const float*)d_in[0];
    const int*   src = (const int*)  d_in[1];
    const int*   dst = (const int*)  d_in[2];
    const float* W0  = (const float*)d_in[3];
    const float* b0  = (const float*)d_in[4];
    const float* W1  = (const float*)d_in[5];
    const float* b1  = (const float*)d_in[6];
    const float* W2  = (const float*)d_in[7];
    const float* b2  = (const float*)d_in[8];
    float* out = (float*)d_out;

    float* h1;  cudaGetSymbolAddress((void**)&h1, g_h1);
    float* h2;  cudaGetSymbolAddress((void**)&h2, g_h2);

    const int scatter_grid = (N_EDGES * 16 + 255) / 256;  // 50000
    const int mlp_grid     = (N_NODES + TR - 1) / TR;     // 782

    deg_kernel<<<(N_EDGES + 255) / 256, 256>>>(dst);
    inv_kernel<<<(N_NODES + 255) / 256, 256>>>();

    scatter_kernel<<<scatter_grid, 256>>>(x, src, dst);
    mlp_kernel<true><<<mlp_grid, 256>>>(x, W0, b0, h1);

    scatter_kernel<<<scatter_grid, 256>>>(h1, src, dst);
    mlp_kernel<true><<<mlp_grid, 256>>>(h1, W1, b1, h2);

    scatter_kernel<<<scatter_grid, 256>>>(h2, src, dst);
    mlp_kernel<false><<<mlp_grid, 256>>>(h2, W2, b2, out);
}

// round 3
// speedup vs baseline: 1.1173x; 1.0361x over previous
#include <cuda_runtime.h>

#define N_NODES 50000
#define N_EDGES 800000
#define D 64
#define TR 64            // rows per MLP block

typedef unsigned long long ull;

// Scratch (allocation-free rule: __device__ globals, zero-initialized at load)
__device__ float g_agg[(size_t)N_NODES * D];
__device__ float g_h1[(size_t)N_NODES * D];
__device__ float g_h2[(size_t)N_NODES * D];
__device__ float g_deg[N_NODES];
__device__ float g_inv[N_NODES];

// packed f32x2 fma: d = a*b + d elementwise on (lo,hi) float pairs (FFMA2, rt=1)
__device__ __forceinline__ void ffma2(ull& d, ull a, ull b) {
    asm("fma.rn.f32x2 %0, %1, %2, %0;" : "+l"(d) : "l"(a), "l"(b));
}

// ---------------------------------------------------------------------------
__global__ void deg_kernel(const int* __restrict__ dst) {
    int e = blockIdx.x * blockDim.x + threadIdx.x;
    if (e < N_EDGES) atomicAdd(&g_deg[dst[e]], 1.0f);
}

__global__ void inv_kernel() {
    int n = blockIdx.x * blockDim.x + threadIdx.x;
    if (n < N_NODES) {
        g_inv[n] = 1.0f / (g_deg[n] + 1.0f);
        g_deg[n] = 0.0f;  // ready for next replay
    }
}

// ---------------------------------------------------------------------------
// Edge scatter: agg[dst] += h[src]. 16 threads/edge, one float4 each.
__global__ void __launch_bounds__(256) scatter_kernel(
        const float* __restrict__ h,
        const int* __restrict__ src,
        const int* __restrict__ dst) {
    int idx = blockIdx.x * blockDim.x + threadIdx.x;
    int e = idx >> 4;
    if (e >= N_EDGES) return;
    int q = idx & 15;
    int s = __ldg(src + e);
    int d = __ldg(dst + e);
    float4 v = __ldg(reinterpret_cast<const float4*>(h + (size_t)s * D) + q);
    float* p = g_agg + (size_t)d * D + (size_t)q * 4;
    asm volatile("red.global.add.v4.f32 [%0], {%1, %2, %3, %4};"
                 :: "l"(p), "f"(v.x), "f"(v.y), "f"(v.z), "f"(v.w)
                 : "memory");
}

// ---------------------------------------------------------------------------
// Fused MLP: v = (agg+h)*inv ; out = relu?(v @ W + b), FFMA2 inner loop.
// Wq smem layout: Wq[c*33 + k2] = (W[2k2][c], W[2k2+1][c]) as float2, so each
// lane streams its column's k-pairs via conflict-free LDS.64. v pairs are
// LDS.64 broadcasts. acc holds (even-k, odd-k) partial sums, merged at end.
// Zeroes g_agg behind itself (each element read exactly once).
template <bool RELU>
__global__ void __launch_bounds__(256) mlp_kernel(
        const float* __restrict__ h,
        const float* __restrict__ W,
        const float* __restrict__ b,
        float* __restrict__ out) {
    __shared__ float2 Wq[D * 33];        // padded stride 33 float2 per column
    __shared__ float vsm[TR * D];
    __shared__ float bs[D];

    int tid = threadIdx.x;
    int rowBase = blockIdx.x * TR;

    // Stage W k-pair-packed per column: Wqf[c*66 + k] = W[k*64 + c]
    float* Wqf = reinterpret_cast<float*>(Wq);
    for (int i = tid; i < D * D; i += 256) {
        int k = i >> 6, c = i & 63;
        Wqf[c * 66 + k] = W[i];
    }
    if (tid < D) bs[tid] = b[tid];

    // Stage v tile: (agg + h) * inv, float4, coalesced; zero agg behind.
    for (int i = tid; i < TR * (D / 4); i += 256) {     // 1024 float4s
        int r = i >> 4;
        int row = rowBase + r;
        if (row < N_NODES) {
            size_t off = (size_t)row * D + (size_t)(i & 15) * 4;
            float4 a  = *reinterpret_cast<float4*>(g_agg + off);
            float4 hh = __ldg(reinterpret_cast<const float4*>(h + off));
            float iv = g_inv[row];
            float4 v;
            v.x = (a.x + hh.x) * iv;
            v.y = (a.y + hh.y) * iv;
            v.z = (a.z + hh.z) * iv;
            v.w = (a.w + hh.w) * iv;
            *reinterpret_cast<float4*>(vsm + (size_t)i * 4) = v;
            *reinterpret_cast<float4*>(g_agg + off) = make_float4(0.f, 0.f, 0.f, 0.f);
        }
    }
    __syncthreads();

    int warp = tid >> 5;
    int lane = tid & 31;
    int r0 = warp * 8;

    ull acc_a[8], acc_b[8];
#pragma unroll
    for (int r = 0; r < 8; r++) { acc_a[r] = 0ull; acc_b[r] = 0ull; }

    const ull* Wa = reinterpret_cast<const ull*>(Wq) + lane * 33;
    const ull* Wb = reinterpret_cast<const ull*>(Wq) + (lane + 32) * 33;
    const ull* vbase = reinterpret_cast<const ull*>(vsm) + r0 * (D / 2);

#pragma unroll
    for (int k2 = 0; k2 < D / 2; k2++) {
        ull wa = Wa[k2];                 // LDS.64 conflict-free
        ull wb = Wb[k2];
#pragma unroll
        for (int r = 0; r < 8; r++) {
            ull vp = vbase[r * (D / 2) + k2];   // LDS.64 broadcast
            ffma2(acc_a[r], vp, wa);
            ffma2(acc_b[r], vp, wb);
        }
    }

    float bias0 = bs[lane], bias1 = bs[lane + 32];
#pragma unroll
    for (int r = 0; r < 8; r++) {
        int row = rowBase + r0 + r;
        if (row < N_NODES) {
            float2 pa = *reinterpret_cast<float2*>(&acc_a[r]);
            float2 pb = *reinterpret_cast<float2*>(&acc_b[r]);
            float o0 = pa.x + pa.y + bias0;
            float o1 = pb.x + pb.y + bias1;
            if (RELU) { o0 = fmaxf(o0, 0.f); o1 = fmaxf(o1, 0.f); }
            out[(size_t)row * D + lane]      = o0;
            out[(size_t)row * D + lane + 32] = o1;
        }
    }
}

// ---------------------------------------------------------------------------
extern "C" void kernel_launch(void* const* d_in, const int* in_sizes, int n_in,
                              void* d_out, int out_size) {
    const float* x   = (const float*)d_in[0];
    const int*   src = (const int*)  d_in[1];
    const int*   dst = (const int*)  d_in[2];
    const float* W0  = (const float*)d_in[3];
    const float* b0  = (const float*)d_in[4];
    const float* W1  = (const float*)d_in[5];
    const float* b1  = (const float*)d_in[6];
    const float* W2  = (const float*)d_in[7];
    const float* b2  = (const float*)d_in[8];
    float* out = (float*)d_out;

    float* h1;  cudaGetSymbolAddress((void**)&h1, g_h1);
    float* h2;  cudaGetSymbolAddress((void**)&h2, g_h2);

    const int scatter_grid = (N_EDGES * 16 + 255) / 256;  // 50000
    const int mlp_grid     = (N_NODES + TR - 1) / TR;     // 782

    deg_kernel<<<(N_EDGES + 255) / 256, 256>>>(dst);
    inv_kernel<<<(N_NODES + 255) / 256, 256>>>();

    scatter_kernel<<<scatter_grid, 256>>>(x, src, dst);
    mlp_kernel<true><<<mlp_grid, 256>>>(x, W0, b0, h1);

    scatter_kernel<<<scatter_grid, 256>>>(h1, src, dst);
    mlp_kernel<true><<<mlp_grid, 256>>>(h1, W1, b1, h2);

    scatter_kernel<<<scatter_grid, 256>>>(h2, src, dst);
    mlp_kernel<false><<<mlp_grid, 256>>>(h2, W2, b2, out);
}